// round 2
// baseline (speedup 1.0000x reference)
#include <cuda_runtime.h>
#include <cstdint>

// ---------------- problem constants ----------------
#define B_    2
#define L_    4096
#define DM    2048      // d_model
#define DSSM  4096
#define DST   128       // d_state
#define NH    64        // heads
#define HD    64        // headdim
#define DCONV 4
#define CHK   64        // chunk length
#define NC    64        // num chunks (L/CHK)
#define DIP   8512      // d_in_proj
#define CDIM  4352      // conv dim
#define BL    8192      // B_*L_

// ---------------- scratch (static device, allocation-free) ----------------
__device__ float g_zx [69730304];   // [BL][DIP]        zxbcdt
__device__ float g_xbc[35651584];   // [BL][CDIM]       conv+silu output
__device__ float g_dt [524288];     // [BL][NH]         softplus(dt)
__device__ float g_ac [524288];     // [b*NC][NH][CHK]  A_cum within chunk
__device__ float g_st [67108864];   // [b*NC][NH][HD][DST] states -> prev (in-place scan)
__device__ float g_y  [33554432];   // [BL][DSSM]       y before gate/norm
__device__ float g_yn [33554432];   // [BL][DSSM]       normalized y

// ---------------- helpers ----------------
__device__ __forceinline__ float siluf(float x) {
    return x / (1.f + __expf(-x));
}
__device__ __forceinline__ float softplusf(float x) {
    return x > 20.f ? x : log1pf(__expf(x));
}

// ---------------- GEMM: C[M,N] = A[M,K] * B[N,K]^T (both row-major, K-contig) ----------------
// 128x128 block, 8x8 per thread, 256 threads, BK=16. M%128==0, K%16==0 assumed; N guarded.
__global__ void __launch_bounds__(256) gemm_abt_kernel(
    const float* __restrict__ A, const float* __restrict__ B,
    float* __restrict__ C, int M, int N, int K)
{
    const int BM = 128, BN = 128, BK = 16;
    __shared__ float As[BK][BM];
    __shared__ float Bs[BK][BN];

    int bm = blockIdx.y * BM;
    int bn = blockIdx.x * BN;
    int tid = threadIdx.x;
    int tx = tid & 15;       // 0..15 (N dir)
    int ty = tid >> 4;       // 0..15 (M dir)

    float acc[8][8];
    #pragma unroll
    for (int i = 0; i < 8; i++)
        #pragma unroll
        for (int j = 0; j < 8; j++) acc[i][j] = 0.f;

    for (int k0 = 0; k0 < K; k0 += BK) {
        // load A tile and B tile: each 128 rows x 16 cols = 512 float4; 2 per thread each
        #pragma unroll
        for (int it = 0; it < 2; it++) {
            int idx = tid + it * 256;
            int row = idx >> 2;
            int c4  = (idx & 3) * 4;
            float4 av = *(const float4*)(A + (size_t)(bm + row) * K + k0 + c4);
            As[c4 + 0][row] = av.x; As[c4 + 1][row] = av.y;
            As[c4 + 2][row] = av.z; As[c4 + 3][row] = av.w;
            int brow = bn + row;
            float4 bv = make_float4(0.f, 0.f, 0.f, 0.f);
            if (brow < N) bv = *(const float4*)(B + (size_t)brow * K + k0 + c4);
            Bs[c4 + 0][row] = bv.x; Bs[c4 + 1][row] = bv.y;
            Bs[c4 + 2][row] = bv.z; Bs[c4 + 3][row] = bv.w;
        }
        __syncthreads();
        #pragma unroll
        for (int kk = 0; kk < BK; kk++) {
            float a[8], b[8];
            #pragma unroll
            for (int i = 0; i < 8; i++) a[i] = As[kk][ty * 8 + i];
            #pragma unroll
            for (int j = 0; j < 8; j++) b[j] = Bs[kk][tx * 8 + j];
            #pragma unroll
            for (int i = 0; i < 8; i++)
                #pragma unroll
                for (int j = 0; j < 8; j++)
                    acc[i][j] += a[i] * b[j];
        }
        __syncthreads();
    }

    #pragma unroll
    for (int i = 0; i < 8; i++) {
        int row = bm + ty * 8 + i;
        #pragma unroll
        for (int j = 0; j < 8; j += 4) {
            int col = bn + tx * 8 + j;
            if (col + 3 < N) {
                *(float4*)(C + (size_t)row * N + col) =
                    make_float4(acc[i][j], acc[i][j+1], acc[i][j+2], acc[i][j+3]);
            } else {
                for (int jj = 0; jj < 4; jj++)
                    if (col + jj < N) C[(size_t)row * N + col + jj] = acc[i][j+jj];
            }
        }
    }
}

// ---------------- causal depthwise conv (width 4) + bias + SiLU over CDIM channels ----------------
__global__ void conv_silu_kernel(const float* __restrict__ conv_w,
                                 const float* __restrict__ conv_b)
{
    int idx = blockIdx.x * blockDim.x + threadIdx.x;
    if (idx >= BL * CDIM) return;
    int ch = idx % CDIM;
    int bl = idx / CDIM;
    int l  = bl & (L_ - 1);

    float s = conv_b[ch];
    const float* wp = conv_w + ch * 4;
    size_t base = (size_t)bl * DIP + DSSM + ch;
    #pragma unroll
    for (int k = 0; k < DCONV; k++) {
        int lp = l - (DCONV - 1) + k;
        if (lp >= 0) s += g_zx[base - (size_t)(DCONV - 1 - k) * DIP] * wp[k];
    }
    g_xbc[(size_t)bl * CDIM + ch] = siluf(s);
}

// ---------------- dt = softplus(raw + bias) ----------------
__global__ void dt_kernel(const float* __restrict__ dt_bias)
{
    int idx = blockIdx.x * blockDim.x + threadIdx.x;  // bl*NH + h
    if (idx >= BL * NH) return;
    int h  = idx & (NH - 1);
    int bl = idx >> 6;
    float x = g_zx[(size_t)bl * DIP + (DIP - NH) + h] + dt_bias[h];
    g_dt[idx] = softplusf(x);
}

// ---------------- per-chunk cumsum of dA = dt*A ----------------
__global__ void acum_kernel(const float* __restrict__ A_log)
{
    int bc = blockIdx.x;          // b*NC + c
    int h  = threadIdx.x;         // 0..63
    float A = -expf(A_log[h]);
    int rowbase = (bc >> 6) * L_ + (bc & (NC - 1)) * CHK;
    float cum = 0.f;
    for (int l = 0; l < CHK; l++) {
        cum += g_dt[(size_t)(rowbase + l) * NH + h] * A;
        g_ac[((size_t)bc * NH + h) * CHK + l] = cum;
    }
}

// ---------------- chunk kernel: CB, Y_diag (+D*x), chunk states ----------------
// one block per (b, chunk), 256 threads, loops all 64 heads. dynamic smem ~113KB.
__global__ void __launch_bounds__(256) chunk_kernel(const float* __restrict__ Dv)
{
    extern __shared__ float sm[];
    float* Bs  = sm;               // [64][128]
    float* Cs  = Bs  + 64 * 128;   // [64][128]
    float* CB  = Cs  + 64 * 128;   // [64][64]
    float* xs  = CB  + 64 * 64;    // [64][64]  (s, p)
    float* Lw  = xs  + 64 * 64;    // [64][64]  (l, s)
    float* ac  = Lw  + 64 * 64;    // [64]
    float* dtl = ac  + 64;         // [64]
    float* vv  = dtl + 64;         // [64]

    int bc  = blockIdx.x;
    int tid = threadIdx.x;
    int rowbase = (bc >> 6) * L_ + (bc & (NC - 1)) * CHK;

    // load B (ch 4096..4223) and C (ch 4224..4351) tiles: 64x128 each
    for (int i = tid; i < 64 * 32; i += 256) {
        int r  = i >> 5;
        int c4 = (i & 31) * 4;
        const float* rp = g_xbc + (size_t)(rowbase + r) * CDIM;
        *(float4*)&Bs[r * 128 + c4] = *(const float4*)(rp + DSSM + c4);
        *(float4*)&Cs[r * 128 + c4] = *(const float4*)(rp + DSSM + DST + c4);
    }
    __syncthreads();

    // CB[l][s] = dot(C[l], B[s]) over 128, 4x4 per thread
    {
        int lt = (tid >> 4) * 4, st = (tid & 15) * 4;
        float acc[4][4];
        #pragma unroll
        for (int i = 0; i < 4; i++)
            #pragma unroll
            for (int j = 0; j < 4; j++) acc[i][j] = 0.f;
        for (int n = 0; n < 128; n++) {
            float a[4], b[4];
            #pragma unroll
            for (int i = 0; i < 4; i++) a[i] = Cs[(lt + i) * 128 + n];
            #pragma unroll
            for (int j = 0; j < 4; j++) b[j] = Bs[(st + j) * 128 + n];
            #pragma unroll
            for (int i = 0; i < 4; i++)
                #pragma unroll
                for (int j = 0; j < 4; j++) acc[i][j] += a[i] * b[j];
        }
        #pragma unroll
        for (int i = 0; i < 4; i++)
            #pragma unroll
            for (int j = 0; j < 4; j++) CB[(lt + i) * 64 + st + j] = acc[i][j];
    }
    __syncthreads();

    for (int h = 0; h < NH; h++) {
        // x tile for this head: [64 pos][64 p]
        for (int i = tid; i < 64 * 16; i += 256) {
            int r  = i >> 4;
            int c4 = (i & 15) * 4;
            *(float4*)&xs[r * 64 + c4] =
                *(const float4*)(g_xbc + (size_t)(rowbase + r) * CDIM + h * HD + c4);
        }
        if (tid < 64) {
            ac[tid]  = g_ac[((size_t)bc * NH + h) * CHK + tid];
            dtl[tid] = g_dt[(size_t)(rowbase + tid) * NH + h];
        }
        __syncthreads();
        if (tid < 64) vv[tid] = __expf(ac[63] - ac[tid]) * dtl[tid];
        // L-weighted matrix: Lw[l][s] = CB[l][s]*exp(ac[l]-ac[s])*dt[s], s<=l
        for (int o = tid; o < 64 * 64; o += 256) {
            int l = o >> 6, s = o & 63;
            Lw[o] = (s <= l) ? CB[o] * __expf(ac[l] - ac[s]) * dtl[s] : 0.f;
        }
        __syncthreads();

        // Y_diag[l][p] = sum_s Lw[l][s]*x[s][p]  (4x4 per thread), + D[h]*x[l][p]
        {
            int lt = (tid >> 4) * 4, pt = (tid & 15) * 4;
            float acc[4][4];
            #pragma unroll
            for (int i = 0; i < 4; i++)
                #pragma unroll
                for (int j = 0; j < 4; j++) acc[i][j] = 0.f;
            for (int s = 0; s < 64; s++) {
                float a[4], xb[4];
                #pragma unroll
                for (int i = 0; i < 4; i++) a[i] = Lw[(lt + i) * 64 + s];
                #pragma unroll
                for (int j = 0; j < 4; j++) xb[j] = xs[s * 64 + pt + j];
                #pragma unroll
                for (int i = 0; i < 4; i++)
                    #pragma unroll
                    for (int j = 0; j < 4; j++) acc[i][j] += a[i] * xb[j];
            }
            float Dh = Dv[h];
            #pragma unroll
            for (int i = 0; i < 4; i++) {
                int l = lt + i;
                size_t yrow = (size_t)(rowbase + l) * DSSM + h * HD;
                #pragma unroll
                for (int j = 0; j < 4; j++) {
                    int p = pt + j;
                    g_y[yrow + p] = acc[i][j] + Dh * xs[l * 64 + p];
                }
            }
        }

        // states[p][n] = sum_l x[l][p]*vv[l]*B[l][n]  (4p x 8n per thread)
        {
            int pr = (tid >> 4) * 4, ncn = (tid & 15) * 8;
            float acc[4][8];
            #pragma unroll
            for (int i = 0; i < 4; i++)
                #pragma unroll
                for (int j = 0; j < 8; j++) acc[i][j] = 0.f;
            for (int l = 0; l < 64; l++) {
                float w = vv[l];
                float xv[4], bn[8];
                #pragma unroll
                for (int i = 0; i < 4; i++) xv[i] = xs[l * 64 + pr + i] * w;
                #pragma unroll
                for (int j = 0; j < 8; j++) bn[j] = Bs[l * 128 + ncn + j];
                #pragma unroll
                for (int i = 0; i < 4; i++)
                    #pragma unroll
                    for (int j = 0; j < 8; j++) acc[i][j] += xv[i] * bn[j];
            }
            size_t sbase = ((size_t)bc * NH + h) * (HD * DST);
            #pragma unroll
            for (int i = 0; i < 4; i++)
                #pragma unroll
                for (int j = 0; j < 8; j += 4)
                    *(float4*)&g_st[sbase + (size_t)(pr + i) * DST + ncn + j] =
                        make_float4(acc[i][j], acc[i][j+1], acc[i][j+2], acc[i][j+3]);
        }
        __syncthreads();  // protect xs/Lw/ac for next head
    }
}

// ---------------- inter-chunk scan (in-place: states -> prev) ----------------
__global__ void __launch_bounds__(256) scan_kernel()
{
    int b = blockIdx.x >> 6;
    int h = blockIdx.x & (NH - 1);
    int tid = threadIdx.x;
    float carry[32];
    #pragma unroll
    for (int k = 0; k < 32; k++) carry[k] = 0.f;

    for (int c = 0; c < NC; c++) {
        int bc = b * NC + c;
        float cd = __expf(g_ac[((size_t)bc * NH + h) * CHK + (CHK - 1)]);
        size_t base = ((size_t)bc * NH + h) * (HD * DST);
        #pragma unroll 4
        for (int k = 0; k < 32; k++) {
            size_t e = base + (size_t)k * 256 + tid;
            float s = g_st[e];
            g_st[e] = carry[k];
            carry[k] = carry[k] * cd + s;
        }
    }
}

// ---------------- Y_off: y += exp(Acum[l]) * (C[l] . prev[p]) ----------------
__global__ void __launch_bounds__(256) yoff_kernel()
{
    __shared__ float Ch[64 * 64];
    __shared__ float Ph[64 * 64];
    __shared__ float acs[64];

    int bc  = blockIdx.x;
    int h   = blockIdx.y;
    int tid = threadIdx.x;
    int rowbase = (bc >> 6) * L_ + (bc & (NC - 1)) * CHK;
    size_t sbase = ((size_t)bc * NH + h) * (HD * DST);

    if (tid < 64) acs[tid] = __expf(g_ac[((size_t)bc * NH + h) * CHK + tid]);

    int lt = (tid >> 4) * 4, pt = (tid & 15) * 4;
    float acc[4][4];
    #pragma unroll
    for (int i = 0; i < 4; i++)
        #pragma unroll
        for (int j = 0; j < 4; j++) acc[i][j] = 0.f;

    for (int half = 0; half < 2; half++) {
        __syncthreads();
        for (int i = tid; i < 64 * 16; i += 256) {
            int r  = i >> 4;
            int c4 = (i & 15) * 4;
            *(float4*)&Ch[r * 64 + c4] =
                *(const float4*)(g_xbc + (size_t)(rowbase + r) * CDIM + DSSM + DST + half * 64 + c4);
            *(float4*)&Ph[r * 64 + c4] =
                *(const float4*)(g_st + sbase + (size_t)r * DST + half * 64 + c4);
        }
        __syncthreads();
        for (int n = 0; n < 64; n++) {
            float a[4], p[4];
            #pragma unroll
            for (int i = 0; i < 4; i++) a[i] = Ch[(lt + i) * 64 + n];
            #pragma unroll
            for (int j = 0; j < 4; j++) p[j] = Ph[(pt + j) * 64 + n];
            #pragma unroll
            for (int i = 0; i < 4; i++)
                #pragma unroll
                for (int j = 0; j < 4; j++) acc[i][j] += a[i] * p[j];
        }
    }

    #pragma unroll
    for (int i = 0; i < 4; i++) {
        int l = lt + i;
        size_t yrow = (size_t)(rowbase + l) * DSSM + h * HD;
        float e = acs[l];
        #pragma unroll
        for (int j = 0; j < 4; j++)
            g_y[yrow + pt + j] += e * acc[i][j];
    }
}

// ---------------- gate (y * silu(z)) + RMSNorm ----------------
__global__ void __launch_bounds__(256) gatenorm_kernel(const float* __restrict__ nw)
{
    int row = blockIdx.x;
    int tid = threadIdx.x;
    float yg[16];
    float ss = 0.f;
    #pragma unroll
    for (int k = 0; k < 16; k++) {
        int i = k * 256 + tid;
        float y = g_y[(size_t)row * DSSM + i];
        float z = g_zx[(size_t)row * DIP + i];
        float v = y * siluf(z);
        yg[k] = v;
        ss += v * v;
    }
    __shared__ float red[256];
    red[tid] = ss;
    __syncthreads();
    for (int off = 128; off; off >>= 1) {
        if (tid < off) red[tid] += red[tid + off];
        __syncthreads();
    }
    float scale = rsqrtf(red[0] / (float)DSSM + 1e-5f);
    #pragma unroll
    for (int k = 0; k < 16; k++) {
        int i = k * 256 + tid;
        g_yn[(size_t)row * DSSM + i] = yg[k] * scale * nw[i];
    }
}

// ---------------- launch ----------------
extern "C" void kernel_launch(void* const* d_in, const int* in_sizes, int n_in,
                              void* d_out, int out_size)
{
    const float* u        = (const float*)d_in[0];
    const float* W_in     = (const float*)d_in[1];
    const float* conv_w   = (const float*)d_in[2];
    const float* conv_b   = (const float*)d_in[3];
    const float* dt_bias  = (const float*)d_in[4];
    const float* A_log    = (const float*)d_in[5];
    const float* Dv       = (const float*)d_in[6];
    const float* norm_w   = (const float*)d_in[7];
    const float* W_out    = (const float*)d_in[8];
    float* out = (float*)d_out;

    float *zx, *yn;
    cudaGetSymbolAddress((void**)&zx, g_zx);
    cudaGetSymbolAddress((void**)&yn, g_yn);

    const int CHUNK_SMEM = (64*128*2 + 64*64*3 + 64*3) * 4;  // 115456 B
    cudaFuncSetAttribute(chunk_kernel,
                         cudaFuncAttributeMaxDynamicSharedMemorySize, CHUNK_SMEM);

    // 1. zxbcdt = u @ W_in^T   [8192 x 8512]
    gemm_abt_kernel<<<dim3((DIP + 127) / 128, BL / 128), 256>>>(u, W_in, zx, BL, DIP, DM);
    // 2. conv + silu
    conv_silu_kernel<<<(BL * CDIM + 255) / 256, 256>>>(conv_w, conv_b);
    // 3. dt softplus
    dt_kernel<<<(BL * NH + 255) / 256, 256>>>(dt_bias);
    // 4. per-chunk A cumsum
    acum_kernel<<<B_ * NC, 64>>>(A_log);
    // 5. chunk-local: CB, Y_diag(+Dx), states
    chunk_kernel<<<B_ * NC, 256, CHUNK_SMEM>>>(Dv);
    // 6. inter-chunk scan (states -> prev, in place)
    scan_kernel<<<B_ * NH, 256>>>();
    // 7. Y_off accumulate
    yoff_kernel<<<dim3(B_ * NC, NH), 256>>>();
    // 8. gate + RMSNorm
    gatenorm_kernel<<<BL, 256>>>(norm_w);
    // 9. out = yn @ W_out^T   [8192 x 2048]
    gemm_abt_kernel<<<dim3(DM / 128, BL / 128), 256>>>(yn, W_out, out, BL, DM, DSSM);
}

// round 5
// speedup vs baseline: 1.9424x; 1.9424x over previous
#include <cuda_runtime.h>
#include <cstdint>

// ---------------- problem constants ----------------
#define B_    2
#define L_    4096
#define DM    2048      // d_model
#define DSSM  4096
#define DST   128       // d_state
#define NH    64        // heads
#define HD    64        // headdim
#define DCONV 4
#define CHK   64        // chunk length
#define NC    64        // num chunks (L/CHK)
#define DIP   8512      // d_in_proj
#define CDIM  4352      // conv dim
#define BL    8192      // B_*L_

// ---------------- scratch (static device, allocation-free) ----------------
__device__ float g_zx [69730304];   // [BL][DIP]        zxbcdt
__device__ float g_xbc[35651584];   // [BL][CDIM]       conv+silu output
__device__ float g_dt [524288];     // [BL][NH]         softplus(dt)
__device__ float g_ac [524288];     // [b*NC][NH][CHK]  A_cum within chunk
__device__ float g_st [67108864];   // [b*NC][NH][HD][DST] states -> prev (in-place scan)
__device__ float g_y  [33554432];   // [BL][DSSM]       y before gate/norm
__device__ float g_yn [33554432];   // [BL][DSSM]       normalized y

// ---------------- helpers ----------------
__device__ __forceinline__ float siluf(float x) {
    return x / (1.f + __expf(-x));
}
__device__ __forceinline__ float softplusf(float x) {
    return x > 20.f ? x : log1pf(__expf(x));
}

// ---------------- cp.async helpers ----------------
__device__ __forceinline__ void cp16(uint32_t dst, const void* src) {
    asm volatile("cp.async.cg.shared.global [%0], [%1], 16;\n" :: "r"(dst), "l"(src));
}
__device__ __forceinline__ void cp16z(uint32_t dst, const void* src, int sz) {
    asm volatile("cp.async.cg.shared.global [%0], [%1], 16, %2;\n"
                 :: "r"(dst), "l"(src), "r"(sz));
}
#define CP_COMMIT() asm volatile("cp.async.commit_group;\n" ::: "memory")
#define CP_WAIT1()  asm volatile("cp.async.wait_group 1;\n" ::: "memory")
#define CP_WAIT0()  asm volatile("cp.async.wait_group 0;\n" ::: "memory")

__device__ __forceinline__ void mma_tf32(float* c, const uint32_t* a, const uint32_t* b) {
    asm volatile(
        "mma.sync.aligned.m16n8k8.row.col.f32.tf32.tf32.f32 "
        "{%0,%1,%2,%3}, {%4,%5,%6,%7}, {%8,%9}, {%0,%1,%2,%3};\n"
        : "+f"(c[0]), "+f"(c[1]), "+f"(c[2]), "+f"(c[3])
        : "r"(a[0]), "r"(a[1]), "r"(a[2]), "r"(a[3]), "r"(b[0]), "r"(b[1]));
}

// ---------------- tf32 mma.sync GEMM: C[M,Nn] = A[M,K] * B[Nn,K]^T ----------------
// 128x128 CTA tile, BK=16, 256 thr (8 warps, 4Mx2N, warp tile 32x64).
// Double-buffered cp.async. M%128==0, K%16==0 assumed; Nn guarded (zero-fill).
#define PITCH 20   // floats per smem row (16 data + 4 pad): conflict-free fragment reads
__global__ void __launch_bounds__(256, 2) gemm_tc(
    const float* __restrict__ A, const float* __restrict__ Bm,
    float* __restrict__ C, int M, int Nn, int K, int tilesN, int group)
{
    __shared__ float As[2][128 * PITCH];
    __shared__ float Bs[2][128 * PITCH];

    int tid = threadIdx.x;
    int wid = tid >> 5, lane = tid & 31;
    int wm = wid & 3, wn = wid >> 2;         // 4 x 2 warps
    int g = lane >> 2, kt = lane & 3;

    // grouped tile mapping for L2 reuse
    int tilesM = M >> 7;
    int pid = blockIdx.x;
    int gsize = group * tilesN;
    int gid = pid / gsize;
    int first = gid * group;
    int gsz = min(group, tilesM - first);
    int rem = pid - gid * gsize;
    int pm = first + rem % gsz;
    int pn = rem / gsz;
    int bm = pm << 7, bn = pn << 7;

    uint32_t sA0 = (uint32_t)__cvta_generic_to_shared(&As[0][0]);
    uint32_t sB0 = (uint32_t)__cvta_generic_to_shared(&Bs[0][0]);
    const uint32_t BUFB = 128 * PITCH * 4;   // bytes per buffer

    // per-thread load slots: 512 16B chunks per tile per buffer
    int lrow = tid >> 2;          // 0..63 (x2 with t)
    int lch  = tid & 3;           // 16B chunk within 64B row

    float acc[2][8][4];
    #pragma unroll
    for (int mt = 0; mt < 2; mt++)
        #pragma unroll
        for (int nt = 0; nt < 8; nt++)
            #pragma unroll
            for (int q = 0; q < 4; q++) acc[mt][nt][q] = 0.f;

    int niter = K >> 4;

    // prologue: fill buffer 0
    {
        #pragma unroll
        for (int t = 0; t < 2; t++) {
            int row = lrow + t * 64;
            uint32_t off = (uint32_t)(row * PITCH * 4 + lch * 16);
            cp16(sA0 + off, A + (size_t)(bm + row) * K + lch * 4);
            int br = bn + row;
            int ok = (br < Nn) ? 16 : 0;
            cp16z(sB0 + off, Bm + (size_t)(ok ? br : 0) * K + lch * 4, ok);
        }
        CP_COMMIT();
    }

    for (int it = 0; it < niter; it++) {
        int buf = it & 1;
        if (it + 1 < niter) {
            int nb = (it + 1) & 1;
            int k0 = (it + 1) << 4;
            #pragma unroll
            for (int t = 0; t < 2; t++) {
                int row = lrow + t * 64;
                uint32_t off = (uint32_t)(nb * BUFB + row * PITCH * 4 + lch * 16);
                cp16(sA0 + off, A + (size_t)(bm + row) * K + k0 + lch * 4);
                int br = bn + row;
                int ok = (br < Nn) ? 16 : 0;
                cp16z(sB0 + off, Bm + (size_t)(ok ? br : 0) * K + k0 + lch * 4, ok);
            }
            CP_COMMIT();
            CP_WAIT1();
        } else {
            CP_WAIT0();
        }
        __syncthreads();

        const uint32_t* as = (const uint32_t*)&As[buf][0];
        const uint32_t* bs = (const uint32_t*)&Bs[buf][0];
        #pragma unroll
        for (int ks = 0; ks < 2; ks++) {
            int kk = ks * 8;
            uint32_t a[2][4], b[8][2];
            #pragma unroll
            for (int mt = 0; mt < 2; mt++) {
                int r0 = wm * 32 + mt * 16;
                a[mt][0] = as[(r0 + g) * PITCH + kk + kt];
                a[mt][1] = as[(r0 + g + 8) * PITCH + kk + kt];
                a[mt][2] = as[(r0 + g) * PITCH + kk + kt + 4];
                a[mt][3] = as[(r0 + g + 8) * PITCH + kk + kt + 4];
            }
            #pragma unroll
            for (int nt = 0; nt < 8; nt++) {
                int c0 = wn * 64 + nt * 8;
                b[nt][0] = bs[(c0 + g) * PITCH + kk + kt];
                b[nt][1] = bs[(c0 + g) * PITCH + kk + kt + 4];
            }
            #pragma unroll
            for (int mt = 0; mt < 2; mt++)
                #pragma unroll
                for (int nt = 0; nt < 8; nt++)
                    mma_tf32(acc[mt][nt], a[mt], b[nt]);
        }
        __syncthreads();
    }

    // epilogue
    #pragma unroll
    for (int mt = 0; mt < 2; mt++) {
        int row = bm + wm * 32 + mt * 16 + g;
        #pragma unroll
        for (int nt = 0; nt < 8; nt++) {
            int col = bn + wn * 64 + nt * 8 + 2 * kt;
            if (col < Nn) {
                *(float2*)(C + (size_t)row * Nn + col) =
                    make_float2(acc[mt][nt][0], acc[mt][nt][1]);
                *(float2*)(C + (size_t)(row + 8) * Nn + col) =
                    make_float2(acc[mt][nt][2], acc[mt][nt][3]);
            }
        }
    }
}

// ---------------- causal depthwise conv (width 4) + bias + SiLU over CDIM channels ----------------
__global__ void conv_silu_kernel(const float* __restrict__ conv_w,
                                 const float* __restrict__ conv_b)
{
    int idx = blockIdx.x * blockDim.x + threadIdx.x;
    if (idx >= BL * CDIM) return;
    int ch = idx % CDIM;
    int bl = idx / CDIM;
    int l  = bl & (L_ - 1);

    float s = conv_b[ch];
    const float* wp = conv_w + ch * 4;
    size_t base = (size_t)bl * DIP + DSSM + ch;
    #pragma unroll
    for (int k = 0; k < DCONV; k++) {
        int lp = l - (DCONV - 1) + k;
        if (lp >= 0) s += g_zx[base - (size_t)(DCONV - 1 - k) * DIP] * wp[k];
    }
    g_xbc[(size_t)bl * CDIM + ch] = siluf(s);
}

// ---------------- dt = softplus(raw + bias) ----------------
__global__ void dt_kernel(const float* __restrict__ dt_bias)
{
    int idx = blockIdx.x * blockDim.x + threadIdx.x;  // bl*NH + h
    if (idx >= BL * NH) return;
    int h  = idx & (NH - 1);
    int bl = idx >> 6;
    float x = g_zx[(size_t)bl * DIP + (DIP - NH) + h] + dt_bias[h];
    g_dt[idx] = softplusf(x);
}

// ---------------- per-chunk cumsum of dA = dt*A ----------------
__global__ void acum_kernel(const float* __restrict__ A_log)
{
    int bc = blockIdx.x;          // b*NC + c
    int h  = threadIdx.x;         // 0..63
    float A = -expf(A_log[h]);
    int rowbase = (bc >> 6) * L_ + (bc & (NC - 1)) * CHK;
    float cum = 0.f;
    for (int l = 0; l < CHK; l++) {
        cum += g_dt[(size_t)(rowbase + l) * NH + h] * A;
        g_ac[((size_t)bc * NH + h) * CHK + l] = cum;
    }
}

// ---------------- chunk kernel: CB, Y_diag (+D*x), chunk states ----------------
__global__ void __launch_bounds__(256) chunk_kernel(const float* __restrict__ Dv)
{
    extern __shared__ float smf[];
    float* Bs  = smf;              // [64][128]
    float* Cs  = Bs  + 64 * 128;   // [64][128]
    float* CB  = Cs  + 64 * 128;   // [64][64]
    float* xs  = CB  + 64 * 64;    // [64][64]  (s, p)
    float* Lw  = xs  + 64 * 64;    // [64][64]  (l, s)
    float* ac  = Lw  + 64 * 64;    // [64]
    float* dtl = ac  + 64;         // [64]
    float* vv  = dtl + 64;         // [64]

    int bc  = blockIdx.x;
    int tid = threadIdx.x;
    int rowbase = (bc >> 6) * L_ + (bc & (NC - 1)) * CHK;

    for (int i = tid; i < 64 * 32; i += 256) {
        int r  = i >> 5;
        int c4 = (i & 31) * 4;
        const float* rp = g_xbc + (size_t)(rowbase + r) * CDIM;
        *(float4*)&Bs[r * 128 + c4] = *(const float4*)(rp + DSSM + c4);
        *(float4*)&Cs[r * 128 + c4] = *(const float4*)(rp + DSSM + DST + c4);
    }
    __syncthreads();

    {
        int lt = (tid >> 4) * 4, st = (tid & 15) * 4;
        float acc[4][4];
        #pragma unroll
        for (int i = 0; i < 4; i++)
            #pragma unroll
            for (int j = 0; j < 4; j++) acc[i][j] = 0.f;
        for (int n = 0; n < 128; n++) {
            float a[4], b[4];
            #pragma unroll
            for (int i = 0; i < 4; i++) a[i] = Cs[(lt + i) * 128 + n];
            #pragma unroll
            for (int j = 0; j < 4; j++) b[j] = Bs[(st + j) * 128 + n];
            #pragma unroll
            for (int i = 0; i < 4; i++)
                #pragma unroll
                for (int j = 0; j < 4; j++) acc[i][j] += a[i] * b[j];
        }
        #pragma unroll
        for (int i = 0; i < 4; i++)
            #pragma unroll
            for (int j = 0; j < 4; j++) CB[(lt + i) * 64 + st + j] = acc[i][j];
    }
    __syncthreads();

    for (int h = 0; h < NH; h++) {
        for (int i = tid; i < 64 * 16; i += 256) {
            int r  = i >> 4;
            int c4 = (i & 15) * 4;
            *(float4*)&xs[r * 64 + c4] =
                *(const float4*)(g_xbc + (size_t)(rowbase + r) * CDIM + h * HD + c4);
        }
        if (tid < 64) {
            ac[tid]  = g_ac[((size_t)bc * NH + h) * CHK + tid];
            dtl[tid] = g_dt[(size_t)(rowbase + tid) * NH + h];
        }
        __syncthreads();
        if (tid < 64) vv[tid] = __expf(ac[63] - ac[tid]) * dtl[tid];
        for (int o = tid; o < 64 * 64; o += 256) {
            int l = o >> 6, s = o & 63;
            Lw[o] = (s <= l) ? CB[o] * __expf(ac[l] - ac[s]) * dtl[s] : 0.f;
        }
        __syncthreads();

        {
            int lt = (tid >> 4) * 4, pt = (tid & 15) * 4;
            float acc[4][4];
            #pragma unroll
            for (int i = 0; i < 4; i++)
                #pragma unroll
                for (int j = 0; j < 4; j++) acc[i][j] = 0.f;
            for (int s = 0; s < 64; s++) {
                float a[4], xb[4];
                #pragma unroll
                for (int i = 0; i < 4; i++) a[i] = Lw[(lt + i) * 64 + s];
                #pragma unroll
                for (int j = 0; j < 4; j++) xb[j] = xs[s * 64 + pt + j];
                #pragma unroll
                for (int i = 0; i < 4; i++)
                    #pragma unroll
                    for (int j = 0; j < 4; j++) acc[i][j] += a[i] * xb[j];
            }
            float Dh = Dv[h];
            #pragma unroll
            for (int i = 0; i < 4; i++) {
                int l = lt + i;
                size_t yrow = (size_t)(rowbase + l) * DSSM + h * HD;
                #pragma unroll
                for (int j = 0; j < 4; j++) {
                    int p = pt + j;
                    g_y[yrow + p] = acc[i][j] + Dh * xs[l * 64 + p];
                }
            }
        }

        {
            int pr = (tid >> 4) * 4, ncn = (tid & 15) * 8;
            float acc[4][8];
            #pragma unroll
            for (int i = 0; i < 4; i++)
                #pragma unroll
                for (int j = 0; j < 8; j++) acc[i][j] = 0.f;
            for (int l = 0; l < 64; l++) {
                float w = vv[l];
                float xv[4], bn[8];
                #pragma unroll
                for (int i = 0; i < 4; i++) xv[i] = xs[l * 64 + pr + i] * w;
                #pragma unroll
                for (int j = 0; j < 8; j++) bn[j] = Bs[l * 128 + ncn + j];
                #pragma unroll
                for (int i = 0; i < 4; i++)
                    #pragma unroll
                    for (int j = 0; j < 8; j++) acc[i][j] += xv[i] * bn[j];
            }
            size_t sbase = ((size_t)bc * NH + h) * (HD * DST);
            #pragma unroll
            for (int i = 0; i < 4; i++)
                #pragma unroll
                for (int j = 0; j < 8; j += 4)
                    *(float4*)&g_st[sbase + (size_t)(pr + i) * DST + ncn + j] =
                        make_float4(acc[i][j], acc[i][j+1], acc[i][j+2], acc[i][j+3]);
        }
        __syncthreads();
    }
}

// ---------------- inter-chunk scan (in-place: states -> prev) ----------------
__global__ void __launch_bounds__(256) scan_kernel()
{
    int b = blockIdx.x >> 6;
    int h = blockIdx.x & (NH - 1);
    int tid = threadIdx.x;
    float carry[32];
    #pragma unroll
    for (int k = 0; k < 32; k++) carry[k] = 0.f;

    for (int c = 0; c < NC; c++) {
        int bc = b * NC + c;
        float cd = __expf(g_ac[((size_t)bc * NH + h) * CHK + (CHK - 1)]);
        size_t base = ((size_t)bc * NH + h) * (HD * DST);
        #pragma unroll 4
        for (int k = 0; k < 32; k++) {
            size_t e = base + (size_t)k * 256 + tid;
            float s = g_st[e];
            g_st[e] = carry[k];
            carry[k] = carry[k] * cd + s;
        }
    }
}

// ---------------- Y_off: y += exp(Acum[l]) * (C[l] . prev[p]) ----------------
__global__ void __launch_bounds__(256) yoff_kernel()
{
    __shared__ float Ch[64 * 64];
    __shared__ float Ph[64 * 64];
    __shared__ float acs[64];

    int bc  = blockIdx.x;
    int h   = blockIdx.y;
    int tid = threadIdx.x;
    int rowbase = (bc >> 6) * L_ + (bc & (NC - 1)) * CHK;
    size_t sbase = ((size_t)bc * NH + h) * (HD * DST);

    if (tid < 64) acs[tid] = __expf(g_ac[((size_t)bc * NH + h) * CHK + tid]);

    int lt = (tid >> 4) * 4, pt = (tid & 15) * 4;
    float acc[4][4];
    #pragma unroll
    for (int i = 0; i < 4; i++)
        #pragma unroll
        for (int j = 0; j < 4; j++) acc[i][j] = 0.f;

    for (int half = 0; half < 2; half++) {
        __syncthreads();
        for (int i = tid; i < 64 * 16; i += 256) {
            int r  = i >> 4;
            int c4 = (i & 15) * 4;
            *(float4*)&Ch[r * 64 + c4] =
                *(const float4*)(g_xbc + (size_t)(rowbase + r) * CDIM + DSSM + DST + half * 64 + c4);
            *(float4*)&Ph[r * 64 + c4] =
                *(const float4*)(g_st + sbase + (size_t)r * DST + half * 64 + c4);
        }
        __syncthreads();
        for (int n = 0; n < 64; n++) {
            float a[4], p[4];
            #pragma unroll
            for (int i = 0; i < 4; i++) a[i] = Ch[(lt + i) * 64 + n];
            #pragma unroll
            for (int j = 0; j < 4; j++) p[j] = Ph[(pt + j) * 64 + n];
            #pragma unroll
            for (int i = 0; i < 4; i++)
                #pragma unroll
                for (int j = 0; j < 4; j++) acc[i][j] += a[i] * p[j];
        }
    }

    #pragma unroll
    for (int i = 0; i < 4; i++) {
        int l = lt + i;
        size_t yrow = (size_t)(rowbase + l) * DSSM + h * HD;
        float e = acs[l];
        #pragma unroll
        for (int j = 0; j < 4; j++)
            g_y[yrow + pt + j] += e * acc[i][j];
    }
}

// ---------------- gate (y * silu(z)) + RMSNorm ----------------
__global__ void __launch_bounds__(256) gatenorm_kernel(const float* __restrict__ nw)
{
    int row = blockIdx.x;
    int tid = threadIdx.x;
    float yg[16];
    float ss = 0.f;
    #pragma unroll
    for (int k = 0; k < 16; k++) {
        int i = k * 256 + tid;
        float y = g_y[(size_t)row * DSSM + i];
        float z = g_zx[(size_t)row * DIP + i];
        float v = y * siluf(z);
        yg[k] = v;
        ss += v * v;
    }
    __shared__ float red[256];
    red[tid] = ss;
    __syncthreads();
    for (int off = 128; off; off >>= 1) {
        if (tid < off) red[tid] += red[tid + off];
        __syncthreads();
    }
    float scale = rsqrtf(red[0] / (float)DSSM + 1e-5f);
    #pragma unroll
    for (int k = 0; k < 16; k++) {
        int i = k * 256 + tid;
        g_yn[(size_t)row * DSSM + i] = yg[k] * scale * nw[i];
    }
}

// ---------------- launch ----------------
extern "C" void kernel_launch(void* const* d_in, const int* in_sizes, int n_in,
                              void* d_out, int out_size)
{
    const float* u        = (const float*)d_in[0];
    const float* W_in     = (const float*)d_in[1];
    const float* conv_w   = (const float*)d_in[2];
    const float* conv_b   = (const float*)d_in[3];
    const float* dt_bias  = (const float*)d_in[4];
    const float* A_log    = (const float*)d_in[5];
    const float* Dv       = (const float*)d_in[6];
    const float* norm_w   = (const float*)d_in[7];
    const float* W_out    = (const float*)d_in[8];
    float* out = (float*)d_out;

    float *zx, *yn;
    cudaGetSymbolAddress((void**)&zx, g_zx);
    cudaGetSymbolAddress((void**)&yn, g_yn);

    const int CHUNK_SMEM = (64*128*2 + 64*64*3 + 64*3) * 4;  // 115456 B
    cudaFuncSetAttribute(chunk_kernel,
                         cudaFuncAttributeMaxDynamicSharedMemorySize, CHUNK_SMEM);

    // 1. zxbcdt = u @ W_in^T   [8192 x 8512] via tf32 mma.sync
    {
        int tilesM = BL / 128, tilesN = (DIP + 127) / 128;  // 64 x 67
        gemm_tc<<<tilesM * tilesN, 256>>>(u, W_in, zx, BL, DIP, DM, tilesN, 8);
    }
    // 2. conv + silu
    conv_silu_kernel<<<(BL * CDIM + 255) / 256, 256>>>(conv_w, conv_b);
    // 3. dt softplus
    dt_kernel<<<(BL * NH + 255) / 256, 256>>>(dt_bias);
    // 4. per-chunk A cumsum
    acum_kernel<<<B_ * NC, 64>>>(A_log);
    // 5. chunk-local: CB, Y_diag(+Dx), states
    chunk_kernel<<<B_ * NC, 256, CHUNK_SMEM>>>(Dv);
    // 6. inter-chunk scan (states -> prev, in place)
    scan_kernel<<<B_ * NH, 256>>>();
    // 7. Y_off accumulate
    yoff_kernel<<<dim3(B_ * NC, NH), 256>>>();
    // 8. gate + RMSNorm
    gatenorm_kernel<<<BL, 256>>>(norm_w);
    // 9. out = yn @ W_out^T   [8192 x 2048] via tf32 mma.sync
    {
        int tilesM = BL / 128, tilesN = DM / 128;  // 64 x 16
        gemm_tc<<<tilesM * tilesN, 256>>>(yn, W_out, out, BL, DM, DSSM, tilesN, 8);
    }
}